// round 1
// baseline (speedup 1.0000x reference)
#include <cuda_runtime.h>
#include <math.h>

#define NT 16384        // tokens = 16*32*32
#define NE 16384        // codes
#define D  64
#define BETA 0.25f

#define BM 128
#define BN 128
#define NCHUNK 8
#define CPC (NE / NCHUNK)    // 2048 codes per chunk
#define NSUB (CPC / BN)      // 16 subtiles per chunk

// ---------------- scratch (static device globals; no allocation) ----------------
__device__ float g_eT[D * NE];        // emb transposed: [c][n]
__device__ float g_enorm[NE];
__device__ float g_znorm[NT];
__device__ float g_pval[NCHUNK * NT];
__device__ int   g_pidx[NCHUNK * NT];
__device__ int   g_idx[NT];
__device__ int   g_counts[NE];
__device__ float g_loss;

// ---------------- prep: transpose emb -> g_eT, compute ||e||^2 ----------------
__global__ void k_prep_e(const float* __restrict__ emb) {
    __shared__ float tile[64 * 65];
    int n0 = blockIdx.x * 64;
    int tid = threadIdx.x;  // 256
    for (int i = tid; i < 64 * 64; i += 256) {
        int n = i >> 6, c = i & 63;
        tile[n * 65 + c] = emb[(n0 + n) * 64 + c];   // coalesced read
    }
    __syncthreads();
    for (int i = tid; i < 64 * 64; i += 256) {
        int c = i >> 6, n = i & 63;
        g_eT[c * NE + n0 + n] = tile[n * 65 + c];    // coalesced write
    }
    if (tid < 64) {
        float s = 0.f;
        for (int c = 0; c < 64; c++) { float v = tile[tid * 65 + c]; s += v * v; }
        g_enorm[n0 + tid] = s;
    }
}

// ---------------- prep: ||z||^2 per token; zero counts/loss ----------------
__global__ void k_prep_z(const float* __restrict__ z) {
    int b = blockIdx.x;        // 16
    int hw = threadIdx.x;      // 1024
    float s = 0.f;
    for (int c = 0; c < 64; c++) {
        float v = z[(b * 64 + c) * 1024 + hw];
        s += v * v;
    }
    g_znorm[b * 1024 + hw] = s;
    g_counts[b * 1024 + hw] = 0;
    if (b == 0 && hw == 0) g_loss = 0.f;
}

// ---------------- main: distance GEMM + fused argmin (per chunk) ----------------
__global__ void __launch_bounds__(256, 2) k_main(const float* __restrict__ z) {
    extern __shared__ float sm[];
    float* zs   = sm;              // [64][128]
    float* es   = sm + 8192;       // [64][128]
    float* ensh = sm + 16384;      // [128]

    int tid = threadIdx.x;
    int tx = tid & 15, ty = tid >> 4;
    int ttile = blockIdx.x >> 3;       // 0..127 token tile
    int chunk = blockIdx.x & 7;        // 0..7 code chunk
    int b   = ttile >> 3;
    int hw0 = (ttile & 7) << 7;
    int tbase = ttile << 7;
    int nbase0 = chunk * CPC;

    // load z tile (k-major: zs[c][m]); z[b][c][h][w] is m-contiguous
    for (int i4 = tid; i4 < 64 * 32; i4 += 256) {
        int c = i4 >> 5, m4 = i4 & 31;
        float4 v = *(const float4*)(z + ((size_t)(b * 64 + c)) * 1024 + hw0 + m4 * 4);
        *(float4*)(zs + c * 128 + m4 * 4) = v;
    }

    float zn[8];
#pragma unroll
    for (int i = 0; i < 8; i++) zn[i] = g_znorm[tbase + ty * 8 + i];

    float bmin[8]; int bidx[8];
#pragma unroll
    for (int i = 0; i < 8; i++) { bmin[i] = 3.0e38f; bidx[i] = 0; }

    for (int st = 0; st < NSUB; ++st) {
        int nb = nbase0 + st * BN;
        __syncthreads();   // protects es reuse + first-iter zs visibility
        for (int i4 = tid; i4 < 64 * 32; i4 += 256) {
            int k = i4 >> 5, p4 = i4 & 31;
            *(float4*)(es + k * 128 + p4 * 4) =
                *(const float4*)(g_eT + (size_t)k * NE + nb + p4 * 4);
        }
        if (tid < 128) ensh[tid] = g_enorm[nb + tid];
        __syncthreads();

        float acc[8][8];
#pragma unroll
        for (int i = 0; i < 8; i++)
#pragma unroll
            for (int j = 0; j < 8; j++) acc[i][j] = 0.f;

#pragma unroll 16
        for (int k = 0; k < 64; k++) {
            float a[8], bb[8];
            *(float4*)&a[0]  = *(float4*)(zs + k * 128 + ty * 8);
            *(float4*)&a[4]  = *(float4*)(zs + k * 128 + ty * 8 + 4);
            *(float4*)&bb[0] = *(float4*)(es + k * 128 + tx * 8);
            *(float4*)&bb[4] = *(float4*)(es + k * 128 + tx * 8 + 4);
#pragma unroll
            for (int i = 0; i < 8; i++)
#pragma unroll
                for (int j = 0; j < 8; j++)
                    acc[i][j] = fmaf(a[i], bb[j], acc[i][j]);
        }

        float en[8];
#pragma unroll
        for (int j = 0; j < 8; j++) en[j] = ensh[tx * 8 + j];

        // d = fl( fl(zn + en) - 2*dot )  — mimics reference rounding structure.
        // Ascending n within thread => strict '<' keeps lowest index on ties.
#pragma unroll
        for (int i = 0; i < 8; i++) {
#pragma unroll
            for (int j = 0; j < 8; j++) {
                float dd = __fsub_rn(__fadd_rn(zn[i], en[j]),
                                     __fmul_rn(2.0f, acc[i][j]));
                int nl = st * BN + tx * 8 + j;
                if (dd < bmin[i]) { bmin[i] = dd; bidx[i] = nl; }
            }
        }
    }

    // cross-thread (tx) reduction per token, index tie-break (lowest n wins)
    __syncthreads();
    float* rv = es;                    // 128*16 floats
    int*   ri = (int*)(es + 2048);     // 128*16 ints
#pragma unroll
    for (int i = 0; i < 8; i++) {
        int m = ty * 8 + i;
        rv[m * 16 + tx] = bmin[i];
        ri[m * 16 + tx] = bidx[i];
    }
    __syncthreads();
    if (tid < 128) {
        float bv = rv[tid * 16]; int bi = ri[tid * 16];
#pragma unroll
        for (int x = 1; x < 16; x++) {
            float v = rv[tid * 16 + x]; int ii = ri[tid * 16 + x];
            if (v < bv || (v == bv && ii < bi)) { bv = v; bi = ii; }
        }
        g_pval[chunk * NT + tbase + tid] = bv;
        g_pidx[chunk * NT + tbase + tid] = nbase0 + bi;
    }
}

// ---------------- merge chunks -> final idx, histogram, idx-as-float out ----------------
__global__ void k_merge(float* __restrict__ out) {
    int t = blockIdx.x * 1024 + threadIdx.x;   // grid 16 x 1024
    float bv = g_pval[t]; int bi = g_pidx[t];
#pragma unroll
    for (int ch = 1; ch < NCHUNK; ch++) {
        float v = g_pval[ch * NT + t]; int ii = g_pidx[ch * NT + t];
        if (v < bv || (v == bv && ii < bi)) { bv = v; bi = ii; }
    }
    g_idx[t] = bi;
    out[1048579 + t] = (float)bi;
    atomicAdd(&g_counts[bi], 1);
}

// ---------------- z_q gather + loss accumulation ----------------
__global__ void k_zq(const float* __restrict__ z, float* __restrict__ out) {
    int p = blockIdx.x;            // 1024 planes = (b,c)
    int b = p >> 6, c = p & 63;
    int tid = threadIdx.x;         // 256
    float ls = 0.f;
    for (int hw = tid; hw < 1024; hw += 256) {
        int t = (b << 10) + hw;
        int id = g_idx[t];
        float v  = g_eT[c * NE + id];
        float zv = z[p * 1024 + hw];
        out[p * 1024 + hw] = v;    // z_q_out[b][c][h][w] (straight-through == z_q)
        float df = v - zv;
        ls += df * df;
    }
    __shared__ float red[8];
    for (int o = 16; o > 0; o >>= 1) ls += __shfl_down_sync(0xffffffff, ls, o);
    if ((tid & 31) == 0) red[tid >> 5] = ls;
    __syncthreads();
    if (tid == 0) {
        float s = 0.f;
        for (int w = 0; w < 8; w++) s += red[w];
        atomicAdd(&g_loss, s);
    }
}

// ---------------- scalars: loss, perplexity, cluster_use ----------------
__global__ void k_final(float* __restrict__ out) {
    int tid = threadIdx.x;   // 256
    float ent = 0.f; int cu = 0;
    for (int n = tid; n < NE; n += 256) {
        int c = g_counts[n];
        if (c > 0) cu++;
        float avg = (float)c * (1.0f / 16384.0f);
        ent += avg * logf(avg + 1e-10f);
    }
    __shared__ float se[256]; __shared__ int sc[256];
    se[tid] = ent; sc[tid] = cu;
    __syncthreads();
    for (int o = 128; o > 0; o >>= 1) {
        if (tid < o) { se[tid] += se[tid + o]; sc[tid] += sc[tid + o]; }
        __syncthreads();
    }
    if (tid == 0) {
        out[1048576] = g_loss * (1.0f + BETA) / 1048576.0f;   // loss
        out[1048577] = expf(-se[0]);                          // perplexity
        out[1048578] = (float)sc[0];                          // cluster_use
    }
}

// ---------------- launch ----------------
extern "C" void kernel_launch(void* const* d_in, const int* in_sizes, int n_in,
                              void* d_out, int out_size) {
    const float* z   = (const float*)d_in[0];   // (16,64,32,32)
    const float* emb = (const float*)d_in[1];   // (16384,64)
    float* out = (float*)d_out;

    cudaFuncSetAttribute(k_main, cudaFuncAttributeMaxDynamicSharedMemorySize, 66048);

    k_prep_e<<<NE / 64, 256>>>(emb);
    k_prep_z<<<16, 1024>>>(z);
    k_main<<<128 * NCHUNK, 256, 66048>>>(z);
    k_merge<<<16, 1024>>>(out);
    k_zq<<<1024, 256>>>(z, out);
    k_final<<<1, 256>>>(out);
}

// round 3
// speedup vs baseline: 2.0445x; 2.0445x over previous
#include <cuda_runtime.h>
#include <cuda_fp16.h>
#include <math.h>
#include <stdint.h>

#define NT 16384
#define NE 16384
#define BETA 0.25f

#define RS 200                    // halves per padded row (192 data + 8 pad)
#define RB 400                    // bytes per row
#define TILE_BYTES (128 * RB)     // 51200
#define CHUNKS (TILE_BYTES / 16)  // 3200

// ---------------- static device scratch ----------------
__device__ __half g_zf[16384 * RS];   // A' = [h_z | l_z | h_z], padded rows
__device__ __half g_ef[16384 * RS];   // B' = [h_E | h_E | l_E], E = 4096*e
__device__ float g_enorm[NE];
__device__ float g_znorm[NT];
__device__ int   g_idx[NT];
__device__ int   g_counts[NE];
__device__ float g_loss;

// ---------------- helpers ----------------
__device__ __forceinline__ uint32_t smem_u32(const void* p) {
    uint32_t a;
    asm("{ .reg .u64 t; cvta.to.shared.u64 t, %1; cvt.u32.u64 %0, t; }" : "=r"(a) : "l"(p));
    return a;
}
__device__ __forceinline__ void split2h(float v, __half& h, __half& l) {
    __half hh = __float2half_rn(v);
    float r = __fsub_rn(v, __half2float(hh));   // exact
    h = hh; l = __float2half_rn(r);
}

#define CP_ASYNC16(dst_u32, src_ptr) \
    asm volatile("cp.async.cg.shared.global [%0], [%1], 16;\n" :: "r"(dst_u32), "l"(src_ptr))
#define CP_COMMIT()  asm volatile("cp.async.commit_group;\n" ::: "memory")
#define CP_WAIT0()   asm volatile("cp.async.wait_group 0;\n" ::: "memory")

#define LDSM_X4(r, addr) \
    asm volatile("ldmatrix.sync.aligned.m8n8.x4.shared.b16 {%0,%1,%2,%3}, [%4];" \
        : "=r"((r)[0]), "=r"((r)[1]), "=r"((r)[2]), "=r"((r)[3]) : "r"(addr))
#define LDSM_X2(r, addr) \
    asm volatile("ldmatrix.sync.aligned.m8n8.x2.shared.b16 {%0,%1}, [%2];" \
        : "=r"((r)[0]), "=r"((r)[1]) : "r"(addr))

__device__ __forceinline__ void mma16816(float* c, const uint32_t* a, const uint32_t* b) {
    asm volatile(
        "mma.sync.aligned.m16n8k16.row.col.f32.f16.f16.f32 "
        "{%0,%1,%2,%3}, {%4,%5,%6,%7}, {%8,%9}, {%0,%1,%2,%3};"
        : "+f"(c[0]), "+f"(c[1]), "+f"(c[2]), "+f"(c[3])
        : "r"(a[0]), "r"(a[1]), "r"(a[2]), "r"(a[3]), "r"(b[0]), "r"(b[1]));
}

// ---------------- prep: split z into fp16 pairs (padded rows); znorm ----------------
__global__ void k_split_z(const float* __restrict__ z) {
    extern __shared__ __half st[];          // 128 * RS halves = 51200 B
    int tile = blockIdx.x;                  // 128 tiles of 128 tokens
    int b = tile >> 3, hw0 = (tile & 7) << 7;
    int tid = threadIdx.x;                  // 256
    for (int idx = tid; idx < 8192; idx += 256) {
        int k = idx >> 7, tl = idx & 127;   // consecutive tid -> consecutive tl (coalesced read)
        float v = z[((size_t)(b * 64 + k) << 10) + hw0 + tl];
        __half h, l; split2h(v, h, l);
        st[tl * RS + k]       = h;
        st[tl * RS + 64 + k]  = l;
        st[tl * RS + 128 + k] = h;
    }
    __syncthreads();
    {
        float4* dst = (float4*)(g_zf + (size_t)tile * 128 * RS);
        const float4* src = (const float4*)st;
        for (int i = tid; i < CHUNKS; i += 256) dst[i] = src[i];
    }
    if (tid < 128) {
        float s = 0.f;
        for (int k = 0; k < 64; k++) {
            float v = z[((size_t)(b * 64 + k) << 10) + hw0 + tid];
            s += v * v;
        }
        g_znorm[(tile << 7) + tid] = s;
    }
    if (tile == 0 && tid == 0) g_loss = 0.f;
}

// ---------------- prep: split E = 4096*e; enorm; zero counts ----------------
__global__ void k_split_e(const float* __restrict__ emb) {
    extern __shared__ __half st[];
    int sub = blockIdx.x;                   // 128 subtiles of 128 codes
    int n0 = sub << 7;
    int tid = threadIdx.x;
    for (int idx = tid; idx < 8192; idx += 256) {
        int nl = idx >> 6, k = idx & 63;    // consecutive tid -> consecutive k (coalesced read)
        float v = emb[(size_t)(n0 + nl) * 64 + k] * 4096.0f;   // exact scale
        __half h, l; split2h(v, h, l);
        st[nl * RS + k]       = h;
        st[nl * RS + 64 + k]  = h;
        st[nl * RS + 128 + k] = l;
    }
    __syncthreads();
    {
        float4* dst = (float4*)(g_ef + (size_t)sub * 128 * RS);
        const float4* src = (const float4*)st;
        for (int i = tid; i < CHUNKS; i += 256) dst[i] = src[i];
    }
    if (tid < 128) {
        float s = 0.f;
        for (int k = 0; k < 64; k++) {
            float v = emb[(size_t)(n0 + tid) * 64 + k];
            s += v * v;
        }
        g_enorm[n0 + tid] = s;
        g_counts[n0 + tid] = 0;
    }
}

// ---------------- main: fp16 mma.sync distance GEMM + fused argmin ----------------
// smem: A [0,51200) | B0 [51200,102400) | B1 [102400,153600)
#define SM_TOT (3 * TILE_BYTES)

__global__ void __launch_bounds__(256, 1) k_mma(float* __restrict__ out) {
    extern __shared__ __align__(16) unsigned char sm[];
    uint32_t sb = smem_u32(sm);
    const uint32_t SA = sb, SB0 = sb + TILE_BYTES, SB1 = sb + 2 * TILE_BYTES;

    int tid = threadIdx.x, lane = tid & 31, wid = tid >> 5;
    int mw = wid & 1, nw = wid >> 1;        // 2 x 4 warp grid
    int mbase = mw * 64, nbw = nw * 32;     // warp tile 64 x 32

    // prolog: A tile + B subtile 0 (linear copies, rows pre-padded in gmem)
    {
        const char* gz = (const char*)(g_zf + (size_t)blockIdx.x * 128 * RS);
        for (int i = tid; i < CHUNKS; i += 256) CP_ASYNC16(SA + i * 16, gz + i * 16);
        const char* ge = (const char*)g_ef;
        for (int i = tid; i < CHUNKS; i += 256) CP_ASYNC16(SB0 + i * 16, ge + i * 16);
        CP_COMMIT(); CP_WAIT0();
    }
    __syncthreads();

    // per-thread rows: r = mbase + mi*16 + rh*8 + (lane>>2)
    float zn[8];
#pragma unroll
    for (int mi = 0; mi < 4; mi++)
#pragma unroll
        for (int rh = 0; rh < 2; rh++)
            zn[mi * 2 + rh] = g_znorm[(blockIdx.x << 7) + mbase + mi * 16 + rh * 8 + (lane >> 2)];

    float bv[8]; int bi[8];
#pragma unroll
    for (int r = 0; r < 8; r++) { bv[r] = 3.0e38f; bi[r] = 0; }

    // ldmatrix base addresses (conflict-free with 400B row stride)
    uint32_t a_base = SA + (uint32_t)(mbase + (lane & 15)) * RB + ((lane >> 4) & 1) * 16;
    uint32_t b_roff = (uint32_t)(nbw + (lane & 7)) * RB + ((lane >> 3) & 1) * 16;

    for (int j = 0; j < 128; j++) {
        uint32_t Bcur  = (j & 1) ? SB1 : SB0;
        uint32_t Bnext = (j & 1) ? SB0 : SB1;

        if (j < 127) {   // prefetch next B, overlapped with this subtile's mma
            const char* src = (const char*)(g_ef + (size_t)(j + 1) * 128 * RS);
            for (int i = tid; i < CHUNKS; i += 256) CP_ASYNC16(Bnext + i * 16, src + i * 16);
            CP_COMMIT();
        }

        float en[8];
#pragma unroll
        for (int ni = 0; ni < 4; ni++) {
            int c0 = nbw + ni * 8 + (lane & 3) * 2;
            en[ni * 2]     = __ldg(&g_enorm[(j << 7) + c0]);
            en[ni * 2 + 1] = __ldg(&g_enorm[(j << 7) + c0 + 1]);
        }

        float acc[4][4][4];
#pragma unroll
        for (int mi = 0; mi < 4; mi++)
#pragma unroll
            for (int ni = 0; ni < 4; ni++)
#pragma unroll
                for (int q = 0; q < 4; q++) acc[mi][ni][q] = 0.f;

        uint32_t b_base = Bcur + b_roff;
#pragma unroll
        for (int ks = 0; ks < 12; ks++) {
            uint32_t a[4][4], b[4][2];
#pragma unroll
            for (int mi = 0; mi < 4; mi++)
                LDSM_X4(a[mi], a_base + mi * 16 * RB + ks * 32);
#pragma unroll
            for (int ni = 0; ni < 4; ni++)
                LDSM_X2(b[ni], b_base + ni * 8 * RB + ks * 32);
#pragma unroll
            for (int mi = 0; mi < 4; mi++)
#pragma unroll
                for (int ni = 0; ni < 4; ni++)
                    mma16816(acc[mi][ni], a[mi], b[ni]);
        }

        // fused epilogue: d = fl(fl(zn+en) - acc*2^-11), running argmin (n ascending)
#pragma unroll
        for (int mi = 0; mi < 4; mi++) {
#pragma unroll
            for (int ni = 0; ni < 4; ni++) {
                int n0 = (j << 7) + nbw + ni * 8 + (lane & 3) * 2;
                float d0 = __fsub_rn(__fadd_rn(zn[mi * 2],     en[ni * 2]),     acc[mi][ni][0] * 0x1p-11f);
                float d1 = __fsub_rn(__fadd_rn(zn[mi * 2],     en[ni * 2 + 1]), acc[mi][ni][1] * 0x1p-11f);
                float d2 = __fsub_rn(__fadd_rn(zn[mi * 2 + 1], en[ni * 2]),     acc[mi][ni][2] * 0x1p-11f);
                float d3 = __fsub_rn(__fadd_rn(zn[mi * 2 + 1], en[ni * 2 + 1]), acc[mi][ni][3] * 0x1p-11f);
                if (d0 < bv[mi * 2])     { bv[mi * 2]     = d0; bi[mi * 2]     = n0; }
                if (d1 < bv[mi * 2])     { bv[mi * 2]     = d1; bi[mi * 2]     = n0 + 1; }
                if (d2 < bv[mi * 2 + 1]) { bv[mi * 2 + 1] = d2; bi[mi * 2 + 1] = n0; }
                if (d3 < bv[mi * 2 + 1]) { bv[mi * 2 + 1] = d3; bi[mi * 2 + 1] = n0 + 1; }
            }
        }

        CP_WAIT0();
        __syncthreads();
    }

    // quad reduce (cols within warp): lanes differing in (lane&3)
#pragma unroll
    for (int r = 0; r < 8; r++) {
#pragma unroll
        for (int off = 1; off <= 2; off <<= 1) {
            float ov = __shfl_xor_sync(0xffffffffu, bv[r], off);
            int   oi = __shfl_xor_sync(0xffffffffu, bi[r], off);
            if (ov < bv[r] || (ov == bv[r] && oi < bi[r])) { bv[r] = ov; bi[r] = oi; }
        }
    }
    __syncthreads();
    float* rv = (float*)(sm + TILE_BYTES);          // reuse B0: 128 rows x 4 nwarps
    int*   ri = (int*)(sm + TILE_BYTES + 2048);
    if ((lane & 3) == 0) {
#pragma unroll
        for (int r = 0; r < 8; r++) {
            int row = mbase + (r >> 1) * 16 + (r & 1) * 8 + (lane >> 2);
            rv[row * 4 + nw] = bv[r];
            ri[row * 4 + nw] = bi[r];
        }
    }
    __syncthreads();
    if (tid < 128) {
        float v = rv[tid * 4]; int ii = ri[tid * 4];
#pragma unroll
        for (int x = 1; x < 4; x++) {
            float ov = rv[tid * 4 + x]; int oi = ri[tid * 4 + x];
            if (ov < v || (ov == v && oi < ii)) { v = ov; ii = oi; }
        }
        int t = (blockIdx.x << 7) + tid;
        g_idx[t] = ii;
        out[1048579 + t] = (float)ii;
        atomicAdd(&g_counts[ii], 1);
    }
}

// ---------------- z_q gather + loss accumulation ----------------
__global__ void k_zq(const float* __restrict__ z, const float* __restrict__ emb,
                     float* __restrict__ out) {
    int p = blockIdx.x;            // 1024 planes = (b,c)
    int b = p >> 6, c = p & 63;
    int tid = threadIdx.x;         // 256
    float ls = 0.f;
    for (int hw = tid; hw < 1024; hw += 256) {
        int t = (b << 10) + hw;
        int id = g_idx[t];
        float v  = emb[(size_t)id * 64 + c];
        float zv = z[(size_t)p * 1024 + hw];
        out[(size_t)p * 1024 + hw] = v;
        float df = v - zv;
        ls += df * df;
    }
    __shared__ float red[8];
    for (int o = 16; o > 0; o >>= 1) ls += __shfl_down_sync(0xffffffff, ls, o);
    if ((tid & 31) == 0) red[tid >> 5] = ls;
    __syncthreads();
    if (tid == 0) {
        float s = 0.f;
        for (int w = 0; w < 8; w++) s += red[w];
        atomicAdd(&g_loss, s);
    }
}

// ---------------- scalars ----------------
__global__ void k_final(float* __restrict__ out) {
    int tid = threadIdx.x;   // 256
    float ent = 0.f; int cu = 0;
    for (int n = tid; n < NE; n += 256) {
        int c = g_counts[n];
        if (c > 0) cu++;
        float avg = (float)c * (1.0f / 16384.0f);
        ent += avg * logf(avg + 1e-10f);
    }
    __shared__ float se[256]; __shared__ int sc[256];
    se[tid] = ent; sc[tid] = cu;
    __syncthreads();
    for (int o = 128; o > 0; o >>= 1) {
        if (tid < o) { se[tid] += se[tid + o]; sc[tid] += sc[tid + o]; }
        __syncthreads();
    }
    if (tid == 0) {
        out[1048576] = g_loss * (1.0f + BETA) / 1048576.0f;
        out[1048577] = expf(-se[0]);
        out[1048578] = (float)sc[0];
    }
}

// ---------------- launch ----------------
extern "C" void kernel_launch(void* const* d_in, const int* in_sizes, int n_in,
                              void* d_out, int out_size) {
    const float* z   = (const float*)d_in[0];   // (16,64,32,32)
    const float* emb = (const float*)d_in[1];   // (16384,64)
    float* out = (float*)d_out;

    cudaFuncSetAttribute(k_split_z, cudaFuncAttributeMaxDynamicSharedMemorySize, TILE_BYTES);
    cudaFuncSetAttribute(k_split_e, cudaFuncAttributeMaxDynamicSharedMemorySize, TILE_BYTES);
    cudaFuncSetAttribute(k_mma,     cudaFuncAttributeMaxDynamicSharedMemorySize, SM_TOT);

    k_split_z<<<128, 256, TILE_BYTES>>>(z);
    k_split_e<<<128, 256, TILE_BYTES>>>(emb);
    k_mma<<<128, 256, SM_TOT>>>(out);
    k_zq<<<1024, 256>>>(z, emb, out);
    k_final<<<1, 256>>>(out);
}